// round 3
// baseline (speedup 1.0000x reference)
#include <cuda_runtime.h>
#include <math_constants.h>

// NonMaxSuppression: 3x3 max-pool NMS mask on (8,1,2048,2048) fp32.
// out[y][x] = 1.0f iff in[y][x] == max3x3(in, y, x)  (pad -inf)
//             && in[y][x] >= 0.6f
//             && 10 <= y < H-10 && 10 <= x < W-10
//
// R3: shfl-free, 8 px/thread. Each thread loads its 8 px (2x float4) plus
// the two overlapping halo scalars (L1/L2 hits on neighbors' lines) and
// computes the horizontal 3-max entirely in its own registers via the
// shared-pairwise-max trick (9+8 FMNMX per 8 px). Warp covers 256 cols ->
// grid = 1024 blocks = ONE resident wave (<= 148 SMs x 8 blocks), killing
// the 1.73-wave tail seen in R2. Depth-1 software pipeline kept.

#define H 2048
#define W 2048
#define ROWS 32
#define REP_THR 0.6f
#define BORDER 10

struct RawRow {
    float v[8];
    float l, r;   // halo px (x-1) and (x+8)
};

__global__ __launch_bounds__(128, 8)
void nms_kernel(const float* __restrict__ in, float* __restrict__ out) {
    const int lane = threadIdx.x;                              // 0..31
    const int seg  = blockIdx.x * blockDim.y + threadIdx.y;    // 0..7
    const int b    = blockIdx.z;
    const int y0   = blockIdx.y * ROWS;

    const int x8 = seg * 256 + lane * 8;

    const float* img = in  + (size_t)b * H * W;
    float*       o   = out + (size_t)b * H * W;

    const bool has_l = (x8 > 0);
    const bool has_r = (x8 + 8 < W);

    auto load_raw = [&](int y) -> RawRow {
        RawRow p;
        int yy = y < 0 ? 0 : (y >= H ? H - 1 : y);
        const float* row = img + (size_t)yy * W + x8;
        float4 a = *reinterpret_cast<const float4*>(row);
        float4 c = *reinterpret_cast<const float4*>(row + 4);
        p.v[0] = a.x; p.v[1] = a.y; p.v[2] = a.z; p.v[3] = a.w;
        p.v[4] = c.x; p.v[5] = c.y; p.v[6] = c.z; p.v[7] = c.w;
        p.l = has_l ? row[-1] : -CUDART_INF_F;
        p.r = has_r ? row[8]  : -CUDART_INF_F;
        return p;
    };

    auto hmax8 = [](const RawRow& p, float hm[8]) {
        float t[9];
        t[0] = fmaxf(p.l, p.v[0]);
        #pragma unroll
        for (int i = 0; i < 7; ++i) t[i + 1] = fmaxf(p.v[i], p.v[i + 1]);
        t[8] = fmaxf(p.v[7], p.r);
        #pragma unroll
        for (int i = 0; i < 8; ++i) hm[i] = fmaxf(t[i], t[i + 1]);
    };

    // Prologue.
    RawRow pm = load_raw(y0 - 1);
    RawRow pc = load_raw(y0);
    RawRow pn = load_raw(y0 + 1);

    float hm_m[8], hm_c[8];
    hmax8(pm, hm_m);
    hmax8(pc, hm_c);
    float vc[8];
    #pragma unroll
    for (int i = 0; i < 8; ++i) vc[i] = pc.v[i];

    // Column border predicates (loop-invariant).
    bool bx[8];
    #pragma unroll
    for (int i = 0; i < 8; ++i)
        bx[i] = (x8 + i >= BORDER) && (x8 + i < W - BORDER);

    #pragma unroll 2
    for (int y = y0; y < y0 + ROWS; ++y) {
        // Next raw load first — fully independent, covers LDG latency.
        RawRow pnn = load_raw(y + 2);

        float hm_p[8];
        hmax8(pn, hm_p);

        const bool by = (y >= BORDER) && (y < H - BORDER);

        float res[8];
        #pragma unroll
        for (int i = 0; i < 8; ++i) {
            float m = fmaxf(hm_m[i], fmaxf(hm_c[i], hm_p[i]));
            res[i] = (by && bx[i] && vc[i] >= REP_THR && vc[i] == m) ? 1.0f : 0.0f;
        }

        float* orow = o + (size_t)y * W + x8;
        __stcs(reinterpret_cast<float4*>(orow),
               make_float4(res[0], res[1], res[2], res[3]));
        __stcs(reinterpret_cast<float4*>(orow + 4),
               make_float4(res[4], res[5], res[6], res[7]));

        #pragma unroll
        for (int i = 0; i < 8; ++i) {
            hm_m[i] = hm_c[i];
            hm_c[i] = hm_p[i];
            vc[i]   = pn.v[i];
        }
        pn = pnn;
    }
}

extern "C" void kernel_launch(void* const* d_in, const int* in_sizes, int n_in,
                              void* d_out, int out_size) {
    const float* in = (const float*)d_in[0];
    float* out = (float*)d_out;
    (void)in_sizes; (void)n_in; (void)out_size;

    dim3 block(32, 4);               // 4 warps, each owns a 256-col segment
    dim3 grid(2, H / ROWS, 8);       // 2 seg-groups x 64 strips x 8 batch = 1024
    nms_kernel<<<grid, block>>>(in, out);
}

// round 4
// speedup vs baseline: 1.0019x; 1.0019x over previous
#include <cuda_runtime.h>
#include <math_constants.h>

// NonMaxSuppression: 3x3 max-pool NMS mask on (8,1,2048,2048) fp32.
// out[y][x] = 1.0f iff in[y][x] == max3x3(in, y, x)  (pad -inf)
//             && in[y][x] >= 0.6f
//             && 10 <= y < H-10 && 10 <= x < W-10
//
// R4: back to the R2 shfl-halo structure (one LDG.128 per thread per row;
// per-thread scalar halo loads in R3 blew up L1 wavefronts). Changes vs R2:
//   - ROWS 32 -> 64: grid 2048 -> 1024 blocks = single resident wave
//     (<= 148 SMs x 8 blocks), removing the 1.73-wave tail.
//   - pipeline depth 1 -> 2: two rows' LDGs in flight per warp at all
//     times, doubling outstanding bytes to cover DRAM latency.

#define H 2048
#define W 2048
#define ROWS 64
#define REP_THR 0.6f
#define BORDER 10

__device__ __forceinline__ float4 hmax4(float4 v, float l, float r) {
    float4 h;
    h.x = fmaxf(l,   fmaxf(v.x, v.y));
    h.y = fmaxf(v.x, fmaxf(v.y, v.z));
    h.z = fmaxf(v.y, fmaxf(v.z, v.w));
    h.w = fmaxf(v.z, fmaxf(v.w, r));
    return h;
}

struct Row {
    float4 v;   // 4 pixels
    float  l;   // left halo  (lane 0 only)
    float  r;   // right halo (lane 31 only)
};

__global__ __launch_bounds__(128, 8)
void nms_kernel(const float* __restrict__ in, float* __restrict__ out) {
    const int lane = threadIdx.x;                              // 0..31
    const int seg  = blockIdx.x * blockDim.y + threadIdx.y;    // 0..15
    const int b    = blockIdx.z;
    const int y0   = blockIdx.y * ROWS;

    const int x4 = seg * 128 + lane * 4;

    const float* img = in  + (size_t)b * H * W;
    float*       o   = out + (size_t)b * H * W;

    const bool edge_l = (lane == 0  && x4 > 0);
    const bool edge_r = (lane == 31 && x4 + 4 < W);

    // Raw load: one LDG.128 per thread; edge scalars predicated to 2 lanes.
    auto load_raw = [&](int y) -> Row {
        Row p;
        int yy = y < 0 ? 0 : (y >= H ? H - 1 : y);
        const float* row = img + (size_t)yy * W;
        p.v = *reinterpret_cast<const float4*>(row + x4);
        p.l = edge_l ? row[x4 - 1] : -CUDART_INF_F;
        p.r = edge_r ? row[x4 + 4] : -CUDART_INF_F;
        return p;
    };

    // Consume: shfl halo exchange + horizontal 3-max. Runs >= 2 iterations
    // after the raw load, so LDG latency is fully covered.
    auto consume = [&](const Row& p) -> float4 {
        float l = __shfl_up_sync(0xffffffffu,   p.v.w, 1);
        float r = __shfl_down_sync(0xffffffffu, p.v.x, 1);
        if (lane == 0)  l = p.l;
        if (lane == 31) r = p.r;
        return hmax4(p.v, l, r);
    };

    // Prologue: consume rows y0-1, y0; keep rows y0+1 and y0+2 in flight.
    Row p_m  = load_raw(y0 - 1);
    Row p_c  = load_raw(y0);
    Row p_n  = load_raw(y0 + 1);   // in flight, consumed at y = y0
    Row p_nn = load_raw(y0 + 2);   // in flight, consumed at y = y0+1

    float4 hm_m  = consume(p_m);
    float4 hm_c  = consume(p_c);
    float4 v_cur = p_c.v;

    const bool bx0 = (x4 + 0 >= BORDER) && (x4 + 0 < W - BORDER);
    const bool bx1 = (x4 + 1 >= BORDER) && (x4 + 1 < W - BORDER);
    const bool bx2 = (x4 + 2 >= BORDER) && (x4 + 2 < W - BORDER);
    const bool bx3 = (x4 + 3 >= BORDER) && (x4 + 3 < W - BORDER);

    #pragma unroll 4
    for (int y = y0; y < y0 + ROWS; ++y) {
        // Issue the y+3 load first — keeps two rows in flight at all times.
        Row p_3 = load_raw(y + 3);

        // Consume the row loaded two iterations ago.
        float4 hm_p = consume(p_n);

        const bool by = (y >= BORDER) && (y < H - BORDER);

        float4 res;
        {
            float m;
            m = fmaxf(hm_m.x, fmaxf(hm_c.x, hm_p.x));
            res.x = (by && bx0 && v_cur.x >= REP_THR && v_cur.x == m) ? 1.0f : 0.0f;
            m = fmaxf(hm_m.y, fmaxf(hm_c.y, hm_p.y));
            res.y = (by && bx1 && v_cur.y >= REP_THR && v_cur.y == m) ? 1.0f : 0.0f;
            m = fmaxf(hm_m.z, fmaxf(hm_c.z, hm_p.z));
            res.z = (by && bx2 && v_cur.z >= REP_THR && v_cur.z == m) ? 1.0f : 0.0f;
            m = fmaxf(hm_m.w, fmaxf(hm_c.w, hm_p.w));
            res.w = (by && bx3 && v_cur.w >= REP_THR && v_cur.w == m) ? 1.0f : 0.0f;
        }

        // Streaming store: output is never re-read.
        __stcs(reinterpret_cast<float4*>(o + (size_t)y * W + x4), res);

        hm_m  = hm_c;
        hm_c  = hm_p;
        v_cur = p_n.v;
        p_n   = p_nn;
        p_nn  = p_3;
    }
}

extern "C" void kernel_launch(void* const* d_in, const int* in_sizes, int n_in,
                              void* d_out, int out_size) {
    const float* in = (const float*)d_in[0];
    float* out = (float*)d_out;
    (void)in_sizes; (void)n_in; (void)out_size;

    dim3 block(32, 4);                 // 4 warps, each owns a 128-col segment
    dim3 grid(16 / 4, H / ROWS, 8);    // 4 x 32 x 8 = 1024 blocks, single wave
    nms_kernel<<<grid, block>>>(in, out);
}

// round 5
// speedup vs baseline: 1.0387x; 1.0368x over previous
#include <cuda_runtime.h>
#include <math_constants.h>

// NonMaxSuppression: 3x3 max-pool NMS mask on (8,1,2048,2048) fp32.
// out[y][x] = 1.0f iff in[y][x] == max3x3(in, y, x)  (pad -inf)
//             && in[y][x] >= 0.6f
//             && 10 <= y < H-10 && 10 <= x < W-10
//
// R5: R2 structure (shfl halos, depth-1 pipeline, ROWS=32) + register cap.
// All R2-R4 variants pinned at 64 regs -> 32 warps/SM -> occ 40% -> DRAM
// stuck at ~65%. __launch_bounds__(128, 16) caps regs at 32/thread so 16
// blocks (64 warps) fit per SM; grid 2048 = 13.8 blocks/SM = one wave at
// ~86% occupancy. TLP now covers DRAM latency instead of per-warp ILP.

#define H 2048
#define W 2048
#define ROWS 32
#define REP_THR 0.6f
#define BORDER 10

__device__ __forceinline__ float4 hmax4(float4 v, float l, float r) {
    float4 h;
    h.x = fmaxf(l,   fmaxf(v.x, v.y));
    h.y = fmaxf(v.x, fmaxf(v.y, v.z));
    h.z = fmaxf(v.y, fmaxf(v.z, v.w));
    h.w = fmaxf(v.z, fmaxf(v.w, r));
    return h;
}

struct Row {
    float4 v;   // 4 pixels
    float  l;   // left halo  (lane 0 only)
    float  r;   // right halo (lane 31 only)
};

__global__ __launch_bounds__(128, 16)
void nms_kernel(const float* __restrict__ in, float* __restrict__ out) {
    const int lane = threadIdx.x;                              // 0..31
    const int seg  = blockIdx.x * blockDim.y + threadIdx.y;    // 0..15
    const int b    = blockIdx.z;
    const int y0   = blockIdx.y * ROWS;

    const int x4 = seg * 128 + lane * 4;

    const float* img = in  + (size_t)b * H * W;
    float*       o   = out + (size_t)b * H * W;

    const bool edge_l = (lane == 0  && x4 > 0);
    const bool edge_r = (lane == 31 && x4 + 4 < W);

    auto load_raw = [&](int y) -> Row {
        Row p;
        int yy = y < 0 ? 0 : (y >= H ? H - 1 : y);
        const float* row = img + (size_t)yy * W;
        p.v = *reinterpret_cast<const float4*>(row + x4);
        p.l = edge_l ? row[x4 - 1] : -CUDART_INF_F;
        p.r = edge_r ? row[x4 + 4] : -CUDART_INF_F;
        return p;
    };

    auto consume = [&](const Row& p) -> float4 {
        float l = __shfl_up_sync(0xffffffffu,   p.v.w, 1);
        float r = __shfl_down_sync(0xffffffffu, p.v.x, 1);
        if (lane == 0)  l = p.l;
        if (lane == 31) r = p.r;
        return hmax4(p.v, l, r);
    };

    // Prologue: rows y0-1, y0 consumed; row y0+1 left in flight.
    Row p_m = load_raw(y0 - 1);
    Row p_c = load_raw(y0);
    Row p_n = load_raw(y0 + 1);

    float4 hm_m  = consume(p_m);
    float4 hm_c  = consume(p_c);
    float4 v_cur = p_c.v;

    const bool bx0 = (x4 + 0 >= BORDER) && (x4 + 0 < W - BORDER);
    const bool bx1 = (x4 + 1 >= BORDER) && (x4 + 1 < W - BORDER);
    const bool bx2 = (x4 + 2 >= BORDER) && (x4 + 2 < W - BORDER);
    const bool bx3 = (x4 + 3 >= BORDER) && (x4 + 3 < W - BORDER);

    #pragma unroll 2
    for (int y = y0; y < y0 + ROWS; ++y) {
        // Next row's load first — independent of everything below.
        Row p_nn = load_raw(y + 2);

        // Consume the row loaded last iteration.
        float4 hm_p = consume(p_n);

        const bool by = (y >= BORDER) && (y < H - BORDER);

        float4 res;
        {
            float m;
            m = fmaxf(hm_m.x, fmaxf(hm_c.x, hm_p.x));
            res.x = (by && bx0 && v_cur.x >= REP_THR && v_cur.x == m) ? 1.0f : 0.0f;
            m = fmaxf(hm_m.y, fmaxf(hm_c.y, hm_p.y));
            res.y = (by && bx1 && v_cur.y >= REP_THR && v_cur.y == m) ? 1.0f : 0.0f;
            m = fmaxf(hm_m.z, fmaxf(hm_c.z, hm_p.z));
            res.z = (by && bx2 && v_cur.z >= REP_THR && v_cur.z == m) ? 1.0f : 0.0f;
            m = fmaxf(hm_m.w, fmaxf(hm_c.w, hm_p.w));
            res.w = (by && bx3 && v_cur.w >= REP_THR && v_cur.w == m) ? 1.0f : 0.0f;
        }

        __stcs(reinterpret_cast<float4*>(o + (size_t)y * W + x4), res);

        hm_m  = hm_c;
        hm_c  = hm_p;
        v_cur = p_n.v;
        p_n   = p_nn;
    }
}

extern "C" void kernel_launch(void* const* d_in, const int* in_sizes, int n_in,
                              void* d_out, int out_size) {
    const float* in = (const float*)d_in[0];
    float* out = (float*)d_out;
    (void)in_sizes; (void)n_in; (void)out_size;

    dim3 block(32, 4);                 // 4 warps, each owns a 128-col segment
    dim3 grid(16 / 4, H / ROWS, 8);    // 4 x 64 x 8 = 2048 blocks
    nms_kernel<<<grid, block>>>(in, out);
}